// round 15
// baseline (speedup 1.0000x reference)
#include <cuda_runtime.h>
#include <cuda_bf16.h>
#include <math.h>
#include <stdint.h>

// ---------------- problem constants ----------------
#define BATCH   32
#define L0      4096
#define L1      2048
#define L2      1024
#define C0      256
#define C1      256
#define C2      512
#define C3      128   // EMB_DIM
#define NCODES  4096
#define NROWS   (BATCH * L2)
#define BN_EPS  1e-5

// limb-plane element counts
#define XQN  ((size_t)BATCH * L0 * C0)
#define H1N  ((size_t)BATCH * L1 * C1)
#define H2N  ((size_t)BATCH * L2 * C2)
#define W1N  ((size_t)3 * C1 * C0)
#define W2N  ((size_t)3 * C2 * C1)
#define W3N  ((size_t)3 * C3 * C2)

// prescales (power-of-2, validated headroom R7-R12)
#define INV_SX 0.03125f
#define INV_SH 0.015625f
#define INV_SW 0.5f
#define FSCALE1 0.0009765625f
#define FSCALE2 0.001953125f
#define FSCALE3 0.001953125f

// ---------------- device scratch ----------------
__device__ float g_bb1[C1];
__device__ float g_bb2[C2];
__device__ float g_bb3[C3];
__device__ float g_zz[(size_t)NROWS * C3];
__device__ float g_esq[NCODES];
__device__ float g_arow[NROWS];
__device__ float g_dummy_codes[NROWS];
__device__ float g_dummy_q[(size_t)NROWS * C3];
__device__ int8_t g_xq[4 * XQN];
__device__ int8_t g_h1q[4 * H1N];
__device__ int8_t g_h2q[4 * H2N];
__device__ int8_t g_w1q[4 * W1N];
__device__ int8_t g_w2q[4 * W2N];
__device__ int8_t g_w3q[4 * W3N];
__device__ __nv_bfloat16 g_zhi[(size_t)NROWS * C3];
__device__ __nv_bfloat16 g_zlo[(size_t)NROWS * C3];
__device__ __nv_bfloat16 g_ehi[(size_t)NCODES * C3];
__device__ __nv_bfloat16 g_elo[(size_t)NCODES * C3];

// ---------------- helpers ----------------
__device__ __forceinline__ void bsplit2(float f, unsigned short& hi, unsigned short& lo)
{
    __nv_bfloat16 b0 = __float2bfloat16_rn(f);
    float r = f - __bfloat162float(b0);
    __nv_bfloat16 b1 = __float2bfloat16_rn(r);
    hi = __bfloat16_as_ushort(b0);
    lo = __bfloat16_as_ushort(b1);
}

__device__ __forceinline__ uint4 pack8u(const unsigned short* s)
{
    uint4 w;
    w.x = (uint32_t)s[0] | ((uint32_t)s[1] << 16);
    w.y = (uint32_t)s[2] | ((uint32_t)s[3] << 16);
    w.z = (uint32_t)s[4] | ((uint32_t)s[5] << 16);
    w.w = (uint32_t)s[6] | ((uint32_t)s[7] << 16);
    return w;
}

__device__ __forceinline__ void mma_bf16(float* c, const uint32_t* a, uint32_t b0, uint32_t b1)
{
    asm volatile(
        "mma.sync.aligned.m16n8k16.row.col.f32.bf16.bf16.f32 "
        "{%0,%1,%2,%3}, {%4,%5,%6,%7}, {%8,%9}, {%0,%1,%2,%3};"
        : "+f"(c[0]), "+f"(c[1]), "+f"(c[2]), "+f"(c[3])
        : "r"(a[0]), "r"(a[1]), "r"(a[2]), "r"(a[3]), "r"(b0), "r"(b1));
}

__device__ __forceinline__ void mma_s8(int* d, const uint32_t* a, uint32_t b0, uint32_t b1)
{
    asm volatile(
        "mma.sync.aligned.m16n8k32.row.col.s32.s8.s8.s32 "
        "{%0,%1,%2,%3}, {%4,%5,%6,%7}, {%8,%9}, {%0,%1,%2,%3};"
        : "+r"(d[0]), "+r"(d[1]), "+r"(d[2]), "+r"(d[3])
        : "r"(a[0]), "r"(a[1]), "r"(a[2]), "r"(a[3]), "r"(b0), "r"(b1));
}

__device__ __forceinline__ uint32_t smem_u32(const void* p)
{
    uint32_t a;
    asm("{ .reg .u64 t; cvta.to.shared.u64 t, %1; cvt.u32.u64 %0, t; }" : "=r"(a) : "l"(p));
    return a;
}

__device__ __forceinline__ void cp_async8(uint32_t dst, const void* src, int nbytes)
{
    asm volatile("cp.async.ca.shared.global [%0], [%1], 8, %2;"
                 :: "r"(dst), "l"(src), "r"(nbytes) : "memory");
}
#define CP_COMMIT() asm volatile("cp.async.commit_group;" ::: "memory")
#define CP_WAIT0()  asm volatile("cp.async.wait_group 0;" ::: "memory")

// 4-limb balanced base-2^8 decomposition (exact, verified R11)
__device__ __forceinline__ void enc8(float v, float invS, signed char* L)
{
    float u = v * invS;
    float mhf = rintf(u * 65536.f);
    float r = fmaf(mhf, -1.52587890625e-05f, u);
    int ml = (int)rintf(r * 4294967296.f);
    int mh = (int)mhf;
    int d0 = ((ml + 128) & 255) - 128;  ml = (ml - d0) >> 8;
    int d1 = ((ml + 128) & 255) - 128;  mh += (ml - d1) >> 8;
    int d2 = ((mh + 128) & 255) - 128;  mh = (mh - d2) >> 8;
    L[0] = (signed char)mh;
    L[1] = (signed char)d2;
    L[2] = (signed char)d1;
    L[3] = (signed char)d0;
}

// ---------------- prep kernels (verified) ----------------
__global__ void fold_enc_kernel(const float* __restrict__ w, const float* __restrict__ bias,
                                const float* __restrict__ g, const float* __restrict__ be,
                                const float* __restrict__ m, const float* __restrict__ v,
                                int8_t* __restrict__ wq, size_t wps,
                                float* __restrict__ bout, int CIN, int COUT)
{
    int idx = blockIdx.x * 256 + threadIdx.x;
    int total = 3 * COUT * CIN;
    if (idx < total) {
        int tap = idx / (COUT * CIN);
        int rem = idx - tap * COUT * CIN;
        int co = rem / CIN;
        int ci = rem - co * CIN;
        float scale = 1.0f;
        if (g) {
            double dinv = (double)g[co] / sqrt((double)v[co] + (double)BN_EPS);
            scale = (float)dinv;
        }
        float val = w[((size_t)co * CIN + ci) * 3 + tap] * scale;
        signed char L[4];
        enc8(val, INV_SW, L);
        #pragma unroll
        for (int p = 0; p < 4; ++p) wq[p * wps + idx] = L[p];
    }
    if (idx < COUT) {
        float bo;
        if (g) {
            double dinv = (double)g[idx] / sqrt((double)v[idx] + (double)BN_EPS);
            bo = (float)((double)bias[idx] * dinv + (double)be[idx] - (double)m[idx] * dinv);
        } else {
            bo = bias[idx];
        }
        bout[idx] = bo;
    }
}

__global__ void esq_kernel(const float* __restrict__ emb)
{
    int j = blockIdx.x * 256 + threadIdx.x;
    if (j < NCODES) {
        const float* e = emb + (size_t)j * C3;
        float s = 0.f;
        #pragma unroll 8
        for (int k = 0; k < C3; ++k) s = fmaf(e[k], e[k], s);
        g_esq[j] = s;
    }
}

__global__ __launch_bounds__(256) void xenc_kernel(const float* __restrict__ x,
                                                   int8_t* __restrict__ q, size_t qps)
{
    __shared__ float tile[32][33];
    int b = blockIdx.z, t0 = blockIdx.x * 32, c0 = blockIdx.y * 32;
    int tx = threadIdx.x & 31, ty = threadIdx.x >> 5;
    #pragma unroll
    for (int i = 0; i < 4; ++i)
        tile[ty + 8 * i][tx] = x[((size_t)b * C0 + c0 + ty + 8 * i) * L0 + t0 + tx];
    __syncthreads();
    int tl = threadIdx.x & 31;
    int c4 = threadIdx.x >> 5;
    signed char L[4][4];
    #pragma unroll
    for (int k = 0; k < 4; ++k) {
        signed char tmp[4];
        enc8(tile[c4 * 4 + k][tl], INV_SX, tmp);
        #pragma unroll
        for (int p = 0; p < 4; ++p) L[p][k] = tmp[p];
    }
    size_t o = ((size_t)b * L0 + t0 + tl) * C0 + c0 + c4 * 4;
    #pragma unroll
    for (int p = 0; p < 4; ++p)
        *(char4*)(q + p * qps + o) = make_char4(L[p][0], L[p][1], L[p][2], L[p][3]);
}

// ---------------- conv via exact int8 IMMA v6: R12 warp code, 64t-tile, 2 CTAs/SM ----------------
// 256 threads / 8 warps (2 warpm x 4 warpn), CTA 64t x 64co, warp m32 x n16.
// Numerics byte-identical to R11/R12 (classes 0..3 persistent int32, scalar-LDS fragments).
template<int CIN, int LIN, int LOUT, int COUT, int STRIDE, bool RELU, bool SPLITOUT>
__global__ __launch_bounds__(256, 2)
void conv_imma6_kernel(const int8_t* __restrict__ Xq, size_t xps,
                       const int8_t* __restrict__ Wq, size_t wps,
                       const float* __restrict__ bias, float fscale, float invSo,
                       int8_t* __restrict__ Yq, size_t yps,
                       float* __restrict__ Yf)
{
    constexpr int NTR = STRIDE * 64 + 2;
    constexpr int RB = 40;
    constexpr int ASTR = NTR * RB;
    constexpr int ASZ  = 4 * ASTR;
    constexpr int BSTR = 64 * RB;
    constexpr int BUFSZ = ASZ + 12 * BSTR;
    constexpr int NC = CIN / 32;
    extern __shared__ int8_t smm[];
    const uint32_t smb = smem_u32(smm);

    const int tid = threadIdx.x;
    const int lane = tid & 31;
    const int wid = tid >> 5;
    const int warpm = wid & 1;
    const int warpn = (wid >> 1) & 3;
    const int g = lane >> 2;
    const int tq = lane & 3;
    const int t0  = blockIdx.x * 64;
    const int co0 = blockIdx.y * 64;
    const int bb  = blockIdx.z;
    const int GB  = STRIDE * t0 - 1;

    int ia0[2][2][4], ia1[2][2][4], ia2[2][2][4], ia3[2][2][4];
    #pragma unroll
    for (int mt = 0; mt < 2; ++mt)
        #pragma unroll
        for (int nt = 0; nt < 2; ++nt)
            #pragma unroll
            for (int q = 0; q < 4; ++q) {
                ia0[mt][nt][q] = 0; ia1[mt][nt][q] = 0;
                ia2[mt][nt][q] = 0; ia3[mt][nt][q] = 0;
            }

    auto issue_loads = [&](int cc, uint32_t dst) {
        for (int i = tid; i < NTR * 4; i += 256) {
            int r = i >> 2, u = i & 3;
            int grow = GB + r;
            bool ok = (grow >= 0 && grow < LIN);
            size_t boff = ok ? (((size_t)bb * LIN + grow) * CIN + cc * 32) + u * 8 : 0;
            #pragma unroll
            for (int p = 0; p < 4; ++p)
                cp_async8(dst + p * ASTR + r * RB + u * 8, Xq + p * xps + boff, ok ? 8 : 0);
        }
        for (int i = tid; i < 3 * 64 * 4; i += 256) {
            int tap = i >> 8, rem = i & 255;
            int r = rem >> 2, u = rem & 3;
            size_t boff = (((size_t)tap * COUT + co0 + r) * CIN + cc * 32) + u * 8;
            #pragma unroll
            for (int p = 0; p < 4; ++p)
                cp_async8(dst + ASZ + (tap * 4 + p) * BSTR + r * RB + u * 8,
                          Wq + p * wps + boff, 8);
        }
    };

    issue_loads(0, smb);
    CP_COMMIT();
    CP_WAIT0();
    __syncthreads();

    for (int cc = 0; cc < NC; ++cc) {
        if (cc + 1 < NC) {
            issue_loads(cc + 1, smb + ((cc + 1) & 1) * BUFSZ);
            CP_COMMIT();
        }
        const int8_t* sbase = smm + (cc & 1) * BUFSZ;

        #pragma unroll
        for (int tap = 0; tap < 3; ++tap) {
            uint32_t af[4][2][4];
            #pragma unroll
            for (int mt = 0; mt < 2; ++mt) {
                int tl = warpm * 32 + mt * 16 + g;
                int ra = STRIDE * tl + tap;
                int ra8 = ra + 8 * STRIDE;
                #pragma unroll
                for (int p = 0; p < 4; ++p) {
                    const int8_t* base = sbase + p * ASTR;
                    af[p][mt][0] = *(const uint32_t*)&base[ra  * RB + tq * 4];
                    af[p][mt][1] = *(const uint32_t*)&base[ra8 * RB + tq * 4];
                    af[p][mt][2] = *(const uint32_t*)&base[ra  * RB + tq * 4 + 16];
                    af[p][mt][3] = *(const uint32_t*)&base[ra8 * RB + tq * 4 + 16];
                }
            }
            #pragma unroll
            for (int nt = 0; nt < 2; ++nt) {
                int rb = warpn * 16 + nt * 8 + g;
                uint32_t bf[4][2];
                #pragma unroll
                for (int p = 0; p < 4; ++p) {
                    const int8_t* base = sbase + ASZ + (tap * 4 + p) * BSTR;
                    bf[p][0] = *(const uint32_t*)&base[rb * RB + tq * 4];
                    bf[p][1] = *(const uint32_t*)&base[rb * RB + tq * 4 + 16];
                }
                // class 0
                mma_s8(ia0[0][nt], af[0][0], bf[0][0], bf[0][1]);
                mma_s8(ia0[1][nt], af[0][1], bf[0][0], bf[0][1]);
                // class 1
                mma_s8(ia1[0][nt], af[0][0], bf[1][0], bf[1][1]);
                mma_s8(ia1[0][nt], af[1][0], bf[0][0], bf[0][1]);
                mma_s8(ia1[1][nt], af[0][1], bf[1][0], bf[1][1]);
                mma_s8(ia1[1][nt], af[1][1], bf[0][0], bf[0][1]);
                // class 2
                mma_s8(ia2[0][nt], af[0][0], bf[2][0], bf[2][1]);
                mma_s8(ia2[0][nt], af[1][0], bf[1][0], bf[1][1]);
                mma_s8(ia2[0][nt], af[2][0], bf[0][0], bf[0][1]);
                mma_s8(ia2[1][nt], af[0][1], bf[2][0], bf[2][1]);
                mma_s8(ia2[1][nt], af[1][1], bf[1][0], bf[1][1]);
                mma_s8(ia2[1][nt], af[2][1], bf[0][0], bf[0][1]);
                // class 3
                mma_s8(ia3[0][nt], af[0][0], bf[3][0], bf[3][1]);
                mma_s8(ia3[0][nt], af[1][0], bf[2][0], bf[2][1]);
                mma_s8(ia3[0][nt], af[2][0], bf[1][0], bf[1][1]);
                mma_s8(ia3[0][nt], af[3][0], bf[0][0], bf[0][1]);
                mma_s8(ia3[1][nt], af[0][1], bf[3][0], bf[3][1]);
                mma_s8(ia3[1][nt], af[1][1], bf[2][0], bf[2][1]);
                mma_s8(ia3[1][nt], af[2][1], bf[1][0], bf[1][1]);
                mma_s8(ia3[1][nt], af[3][1], bf[0][0], bf[0][1]);
            }
        }
        CP_WAIT0();
        __syncthreads();
    }

    // ---- epilogue (identical math to R11/R12) ----
    #pragma unroll
    for (int nt = 0; nt < 2; ++nt) {
        int cog = co0 + warpn * 16 + nt * 8 + tq * 2;
        float b0 = __ldg(&bias[cog]);
        float b1 = __ldg(&bias[cog + 1]);
        #pragma unroll
        for (int mt = 0; mt < 2; ++mt) {
            #pragma unroll
            for (int half = 0; half < 2; ++half) {
                int t = t0 + warpm * 32 + mt * 16 + g + half * 8;
                int q0 = half * 2, q1 = half * 2 + 1;
                float s0 = __int2float_rn(ia0[mt][nt][q0])
                         + __int2float_rn(ia1[mt][nt][q0]) * 0.00390625f
                         + __int2float_rn(ia2[mt][nt][q0]) * 1.52587890625e-05f
                         + __int2float_rn(ia3[mt][nt][q0]) * 5.9604644775390625e-08f;
                float s1 = __int2float_rn(ia0[mt][nt][q1])
                         + __int2float_rn(ia1[mt][nt][q1]) * 0.00390625f
                         + __int2float_rn(ia2[mt][nt][q1]) * 1.52587890625e-05f
                         + __int2float_rn(ia3[mt][nt][q1]) * 5.9604644775390625e-08f;
                float v0 = fmaf(s0, fscale, b0);
                float v1 = fmaf(s1, fscale, b1);
                if (RELU) {
                    v0 = (v0 >= 0.f) ? v0 : 0.01f * v0;
                    v1 = (v1 >= 0.f) ? v1 : 0.01f * v1;
                }
                if (SPLITOUT) {
                    signed char La[4], Lb[4];
                    enc8(v0, invSo, La);
                    enc8(v1, invSo, Lb);
                    size_t o = ((size_t)bb * LOUT + t) * COUT + cog;
                    #pragma unroll
                    for (int p = 0; p < 4; ++p) {
                        unsigned short pk = (unsigned short)((unsigned char)La[p]
                                          | ((unsigned short)(unsigned char)Lb[p] << 8));
                        *(unsigned short*)(Yq + p * yps + o) = pk;
                    }
                } else {
                    *(float2*)(Yf + ((size_t)bb * LOUT + t) * COUT + cog) = make_float2(v0, v1);
                }
            }
        }
    }
}

// ---------------- VQ splits (verified R3) ----------------
__global__ __launch_bounds__(256) void split_z_kernel(const float* __restrict__ zz)
{
    int idx = blockIdx.x * 256 + threadIdx.x;
    int row = idx >> 4, gs = idx & 15;
    const float* zr = zz + (size_t)row * C3 + gs * 8;
    float4 p0 = *(const float4*)zr;
    float4 p1 = *(const float4*)(zr + 4);
    float v[8] = {p0.x, p0.y, p0.z, p0.w, p1.x, p1.y, p1.z, p1.w};
    unsigned short h[8], l[8];
    #pragma unroll
    for (int e = 0; e < 8; ++e) bsplit2(v[e], h[e], l[e]);
    ((uint4*)g_zhi)[(size_t)row * 16 + gs] = pack8u(h);
    ((uint4*)g_zlo)[(size_t)row * 16 + gs] = pack8u(l);
    if (gs == 0) {
        const float* zf = zz + (size_t)row * C3;
        float a = 0.f;
        #pragma unroll 8
        for (int k = 0; k < C3; ++k) a = fmaf(zf[k], zf[k], a);
        g_arow[row] = a;
    }
}

__global__ __launch_bounds__(256) void split_e_kernel(const float* __restrict__ emb)
{
    int idx = blockIdx.x * 256 + threadIdx.x;
    int row = idx >> 4, gs = idx & 15;
    const float* er = emb + (size_t)row * C3 + gs * 8;
    float4 p0 = *(const float4*)er;
    float4 p1 = *(const float4*)(er + 4);
    float v[8] = {p0.x, p0.y, p0.z, p0.w, p1.x, p1.y, p1.z, p1.w};
    unsigned short h[8], l[8];
    #pragma unroll
    for (int e = 0; e < 8; ++e) bsplit2(v[e], h[e], l[e]);
    ((uint4*)g_ehi)[(size_t)row * 16 + gs] = pack8u(h);
    ((uint4*)g_elo)[(size_t)row * 16 + gs] = pack8u(l);
}

// ---------------- VQ on mma.sync (verified R3, unchanged) ----------------
#define ZH_OFF 0
#define ZL_OFF 34816
#define EH_OFF 69632
#define EL_OFF 87040
#define JF_OFF 104448
#define RV_OFF 104960
#define RJ_OFF 105984
#define VQ_DYN 107520
#define ROWPAD 272

__global__ __launch_bounds__(256, 1)
void vq_mma_kernel(const float* __restrict__ esq, const float* __restrict__ arow,
                   const float* __restrict__ emb,
                   float* __restrict__ codes, float* __restrict__ quant)
{
    extern __shared__ char smc[];
    const int tid = threadIdx.x;
    const int lane = tid & 31;
    const int wid = tid >> 5;
    const int warp_m = wid & 3;
    const int warp_n = wid >> 2;
    const int g = lane >> 2;
    const int tq = lane & 3;
    const int n0 = blockIdx.x * 128;
    const int mbase = warp_m * 32;

    for (int i = tid; i < 128 * 32; i += 256) {
        int row = i >> 5, u = i & 31;
        ((uint2*)(smc + ZH_OFF))[row * 34 + u] = ((const uint2*)g_zhi)[(size_t)(n0 + row) * 32 + u];
        ((uint2*)(smc + ZL_OFF))[row * 34 + u] = ((const uint2*)g_zlo)[(size_t)(n0 + row) * 32 + u];
    }

    float aval[4];
    #pragma unroll
    for (int s = 0; s < 4; ++s)
        aval[s] = __ldg(&arow[n0 + mbase + (s >> 1) * 16 + (s & 1) * 8 + g]);

    float best[4] = {3.4e38f, 3.4e38f, 3.4e38f, 3.4e38f};
    int   bj[4]   = {0, 0, 0, 0};

    for (int c = 0; c < 64; ++c) {
        __syncthreads();
        for (int i = tid; i < 64 * 32; i += 256) {
            int row = i >> 5, u = i & 31;
            ((uint2*)(smc + EH_OFF))[row * 34 + u] = ((const uint2*)g_ehi)[(size_t)(c * 64 + row) * 32 + u];
            ((uint2*)(smc + EL_OFF))[row * 34 + u] = ((const uint2*)g_elo)[(size_t)(c * 64 + row) * 32 + u];
        }
        __syncthreads();

        float acc[2][4][4];
        #pragma unroll
        for (int mt = 0; mt < 2; ++mt)
            #pragma unroll
            for (int nt = 0; nt < 4; ++nt)
                #pragma unroll
                for (int q = 0; q < 4; ++q) acc[mt][nt][q] = 0.f;

        #pragma unroll
        for (int ks = 0; ks < 8; ++ks) {
            const int k0 = ks * 16;
            uint32_t ah[2][4], al[2][4];
            #pragma unroll
            for (int mt = 0; mt < 2; ++mt) {
                int r0 = mbase + mt * 16 + g;
                int cb = (k0 + tq * 2) * 2;
                ah[mt][0] = *(const uint32_t*)(smc + ZH_OFF + r0 * ROWPAD + cb);
                ah[mt][1] = *(const uint32_t*)(smc + ZH_OFF + (r0 + 8) * ROWPAD + cb);
                ah[mt][2] = *(const uint32_t*)(smc + ZH_OFF + r0 * ROWPAD + cb + 16);
                ah[mt][3] = *(const uint32_t*)(smc + ZH_OFF + (r0 + 8) * ROWPAD + cb + 16);
                al[mt][0] = *(const uint32_t*)(smc + ZL_OFF + r0 * ROWPAD + cb);
                al[mt][1] = *(const uint32_t*)(smc + ZL_OFF + (r0 + 8) * ROWPAD + cb);
                al[mt][2] = *(const uint32_t*)(smc + ZL_OFF + r0 * ROWPAD + cb + 16);
                al[mt][3] = *(const uint32_t*)(smc + ZL_OFF + (r0 + 8) * ROWPAD + cb + 16);
            }
            #pragma unroll
            for (int nt = 0; nt < 4; ++nt) {
                int nrow = warp_n * 32 + nt * 8 + g;
                int cb = (k0 + tq * 2) * 2;
                uint32_t bh0 = *(const uint32_t*)(smc + EH_OFF + nrow * ROWPAD + cb);
                uint32_t bh1 = *(const uint32_t*)(smc + EH_OFF + nrow * ROWPAD + cb + 16);
                uint32_t bl0 = *(const uint32_t*)(smc + EL_OFF + nrow * ROWPAD + cb);
                uint32_t bl1 = *(const uint32_t*)(smc + EL_OFF + nrow * ROWPAD + cb + 16);
                #pragma unroll
                for (int mt = 0; mt < 2; ++mt) {
                    mma_bf16(acc[mt][nt], ah[mt], bh0, bh1);
                    mma_bf16(acc[mt][nt], ah[mt], bl0, bl1);
                    mma_bf16(acc[mt][nt], al[mt], bh0, bh1);
                }
            }
        }

        #pragma unroll
        for (int nt = 0; nt < 4; ++nt) {
            int jb = c * 64 + warp_n * 32 + nt * 8 + tq * 2;
            float e0 = __ldg(&esq[jb]);
            float e1 = __ldg(&esq[jb + 1]);
            #pragma unroll
            for (int mt = 0; mt < 2; ++mt) {
                int s0 = mt * 2, s1 = mt * 2 + 1;
                float d;
                d = (aval[s0] + e0) - 2.0f * acc[mt][nt][0];
                if (d < best[s0]) { best[s0] = d; bj[s0] = jb; }
                d = (aval[s0] + e1) - 2.0f * acc[mt][nt][1];
                if (d < best[s0]) { best[s0] = d; bj[s0] = jb + 1; }
                d = (aval[s1] + e0) - 2.0f * acc[mt][nt][2];
                if (d < best[s1]) { best[s1] = d; bj[s1] = jb; }
                d = (aval[s1] + e1) - 2.0f * acc[mt][nt][3];
                if (d < best[s1]) { best[s1] = d; bj[s1] = jb + 1; }
            }
        }
    }

    #pragma unroll
    for (int s = 0; s < 4; ++s) {
        #pragma unroll
        for (int off = 2; off >= 1; off >>= 1) {
            float ov = __shfl_xor_sync(0xffffffffu, best[s], off);
            int   oj = __shfl_xor_sync(0xffffffffu, bj[s],   off);
            if (ov < best[s] || (ov == best[s] && oj < bj[s])) { best[s] = ov; bj[s] = oj; }
        }
    }
    float* rv = (float*)(smc + RV_OFF);
    int*   rj = (int*)(smc + RJ_OFF);
    if (tq == 0) {
        #pragma unroll
        for (int s = 0; s < 4; ++s) {
            int row = mbase + (s >> 1) * 16 + (s & 1) * 8 + g;
            rv[row * 2 + warp_n] = best[s];
            rj[row * 2 + warp_n] = bj[s];
        }
    }
    __syncthreads();

    int* jf = (int*)(smc + JF_OFF);
    if (tid < 128) {
        float v0 = rv[tid * 2], v1 = rv[tid * 2 + 1];
        int   j0 = rj[tid * 2], j1 = rj[tid * 2 + 1];
        int j = (v1 < v0 || (v1 == v0 && j1 < j0)) ? j1 : j0;
        jf[tid] = j;
        codes[n0 + tid] = (float)j;
    }
    __syncthreads();

    for (int i = tid; i < 128 * 32; i += 256) {
        int row = i >> 5, q = i & 31;
        int j = jf[row];
        float4 v = __ldg((const float4*)emb + (size_t)j * 32 + q);
        ((float4*)quant)[(size_t)(n0 + row) * 32 + q] = v;
    }
}

// ---------------- host launch ----------------
static void* sym(const void* s) { void* p = nullptr; cudaGetSymbolAddress(&p, s); return p; }

#define C12_SMEM (2 * (4 * 130 * 40 + 12 * 64 * 40))   // 103040
#define C3_SMEM  (2 * (4 * 66 * 40 + 12 * 64 * 40))    // 82560

extern "C" void kernel_launch(void* const* d_in, const int* in_sizes, int n_in,
                              void* d_out, int out_size)
{
    const float* x       = (const float*)d_in[0];
    const float* conv1_w = (const float*)d_in[1];
    const float* conv1_b = (const float*)d_in[2];
    const float* bn1_g   = (const float*)d_in[3];
    const float* bn1_b   = (const float*)d_in[4];
    const float* bn1_m   = (const float*)d_in[5];
    const float* bn1_v   = (const float*)d_in[6];
    const float* conv2_w = (const float*)d_in[7];
    const float* conv2_b = (const float*)d_in[8];
    const float* bn2_g   = (const float*)d_in[9];
    const float* bn2_b   = (const float*)d_in[10];
    const float* bn2_m   = (const float*)d_in[11];
    const float* bn2_v   = (const float*)d_in[12];
    const float* conv3_w = (const float*)d_in[13];
    const float* conv3_b = (const float*)d_in[14];
    const float* emb     = (const float*)d_in[15];

    float* bb1 = (float*)sym(g_bb1);
    float* bb2 = (float*)sym(g_bb2);
    float* bb3 = (float*)sym(g_bb3);
    float* zz  = (float*)sym(g_zz);
    float* esq = (float*)sym(g_esq);
    float* arw = (float*)sym(g_arow);
    int8_t* xq  = (int8_t*)sym(g_xq);
    int8_t* h1q = (int8_t*)sym(g_h1q);
    int8_t* h2q = (int8_t*)sym(g_h2q);
    int8_t* w1q = (int8_t*)sym(g_w1q);
    int8_t* w2q = (int8_t*)sym(g_w2q);
    int8_t* w3q = (int8_t*)sym(g_w3q);

    float* out = (float*)d_out;
    float* codes_ptr;
    float* quant_ptr;
    const int FULL = NROWS + NROWS * C3;
    if (out_size >= FULL)            { codes_ptr = out; quant_ptr = out + NROWS; }
    else if (out_size == NROWS * C3) { codes_ptr = (float*)sym(g_dummy_codes); quant_ptr = out; }
    else if (out_size == NROWS)      { codes_ptr = out; quant_ptr = (float*)sym(g_dummy_q); }
    else                             { codes_ptr = out; quant_ptr = out + NROWS; }

    cudaFuncSetAttribute(vq_mma_kernel, cudaFuncAttributeMaxDynamicSharedMemorySize, VQ_DYN);
    cudaFuncSetAttribute((const void*)conv_imma6_kernel<C0, L0, L1, C1, 2, true, true>,
                         cudaFuncAttributeMaxDynamicSharedMemorySize, C12_SMEM);
    cudaFuncSetAttribute((const void*)conv_imma6_kernel<C1, L1, L2, C2, 2, true, true>,
                         cudaFuncAttributeMaxDynamicSharedMemorySize, C12_SMEM);
    cudaFuncSetAttribute((const void*)conv_imma6_kernel<C2, L2, L2, C3, 1, false, false>,
                         cudaFuncAttributeMaxDynamicSharedMemorySize, C3_SMEM);

    // Launch order keeps conv1 at the ncu-captured index.
    {
        dim3 gx(L0 / 32, C0 / 32, BATCH);
        xenc_kernel<<<gx, 256>>>(x, xq, XQN);
    }
    fold_enc_kernel<<<(3 * C1 * C0 + 255) / 256, 256>>>(conv1_w, conv1_b, bn1_g, bn1_b, bn1_m, bn1_v,
                                                        w1q, W1N, bb1, C0, C1);
    fold_enc_kernel<<<(3 * C2 * C1 + 255) / 256, 256>>>(conv2_w, conv2_b, bn2_g, bn2_b, bn2_m, bn2_v,
                                                        w2q, W2N, bb2, C1, C2);
    {
        dim3 g1(L1 / 64, C1 / 64, BATCH);
        conv_imma6_kernel<C0, L0, L1, C1, 2, true, true><<<g1, 256, C12_SMEM>>>(
            xq, XQN, w1q, W1N, bb1, FSCALE1, INV_SH, h1q, H1N, nullptr);
    }
    fold_enc_kernel<<<(3 * C3 * C2 + 255) / 256, 256>>>(conv3_w, conv3_b, nullptr, nullptr, nullptr, nullptr,
                                                        w3q, W3N, bb3, C2, C3);
    esq_kernel<<<(NCODES + 255) / 256, 256>>>(emb);
    split_e_kernel<<<(NCODES * 16) / 256, 256>>>(emb);
    {
        dim3 g2(L2 / 64, C2 / 64, BATCH);
        conv_imma6_kernel<C1, L1, L2, C2, 2, true, true><<<g2, 256, C12_SMEM>>>(
            h1q, H1N, w2q, W2N, bb2, FSCALE2, INV_SH, h2q, H2N, nullptr);
    }
    {
        dim3 g3(L2 / 64, C3 / 64, BATCH);
        conv_imma6_kernel<C2, L2, L2, C3, 1, false, false><<<g3, 256, C3_SMEM>>>(
            h2q, H2N, w3q, W3N, bb3, FSCALE3, 0.f, nullptr, 0, zz);
    }
    split_z_kernel<<<(NROWS * 16) / 256, 256>>>(zz);
    vq_mma_kernel<<<NROWS / 128, 256, VQ_DYN>>>(esq, arw, emb, codes_ptr, quant_ptr);
}

// round 16
// speedup vs baseline: 1.1006x; 1.1006x over previous
#include <cuda_runtime.h>
#include <cuda_bf16.h>
#include <math.h>
#include <stdint.h>

// ---------------- problem constants ----------------
#define BATCH   32
#define L0      4096
#define L1      2048
#define L2      1024
#define C0      256
#define C1      256
#define C2      512
#define C3      128   // EMB_DIM
#define NCODES  4096
#define NROWS   (BATCH * L2)
#define BN_EPS  1e-5

// limb-plane element counts
#define XQN  ((size_t)BATCH * L0 * C0)
#define H1N  ((size_t)BATCH * L1 * C1)
#define H2N  ((size_t)BATCH * L2 * C2)
#define W1N  ((size_t)3 * C1 * C0)
#define W2N  ((size_t)3 * C2 * C1)
#define W3N  ((size_t)3 * C3 * C2)

// prescales (power-of-2, validated headroom R7-R12)
#define INV_SX 0.03125f
#define INV_SH 0.015625f
#define INV_SW 0.5f
#define FSCALE1 0.0009765625f
#define FSCALE2 0.001953125f
#define FSCALE3 0.001953125f

// ---------------- device scratch ----------------
__device__ float g_bb1[C1];
__device__ float g_bb2[C2];
__device__ float g_bb3[C3];
__device__ float g_zz[(size_t)NROWS * C3];
__device__ float g_esq[NCODES];
__device__ float g_arow[NROWS];
__device__ float g_dummy_codes[NROWS];
__device__ float g_dummy_q[(size_t)NROWS * C3];
__device__ int8_t g_xq[4 * XQN];
__device__ int8_t g_h1q[4 * H1N];
__device__ int8_t g_h2q[4 * H2N];
__device__ int8_t g_w1q[4 * W1N];
__device__ int8_t g_w2q[4 * W2N];
__device__ int8_t g_w3q[4 * W3N];
__device__ __nv_bfloat16 g_zhi[(size_t)NROWS * C3];
__device__ __nv_bfloat16 g_zlo[(size_t)NROWS * C3];
__device__ __nv_bfloat16 g_ehi[(size_t)NCODES * C3];
__device__ __nv_bfloat16 g_elo[(size_t)NCODES * C3];

// ---------------- helpers ----------------
__device__ __forceinline__ void bsplit2(float f, unsigned short& hi, unsigned short& lo)
{
    __nv_bfloat16 b0 = __float2bfloat16_rn(f);
    float r = f - __bfloat162float(b0);
    __nv_bfloat16 b1 = __float2bfloat16_rn(r);
    hi = __bfloat16_as_ushort(b0);
    lo = __bfloat16_as_ushort(b1);
}

__device__ __forceinline__ uint4 pack8u(const unsigned short* s)
{
    uint4 w;
    w.x = (uint32_t)s[0] | ((uint32_t)s[1] << 16);
    w.y = (uint32_t)s[2] | ((uint32_t)s[3] << 16);
    w.z = (uint32_t)s[4] | ((uint32_t)s[5] << 16);
    w.w = (uint32_t)s[6] | ((uint32_t)s[7] << 16);
    return w;
}

__device__ __forceinline__ void mma_bf16(float* c, const uint32_t* a, uint32_t b0, uint32_t b1)
{
    asm volatile(
        "mma.sync.aligned.m16n8k16.row.col.f32.bf16.bf16.f32 "
        "{%0,%1,%2,%3}, {%4,%5,%6,%7}, {%8,%9}, {%0,%1,%2,%3};"
        : "+f"(c[0]), "+f"(c[1]), "+f"(c[2]), "+f"(c[3])
        : "r"(a[0]), "r"(a[1]), "r"(a[2]), "r"(a[3]), "r"(b0), "r"(b1));
}

__device__ __forceinline__ void mma_s8(int* d, const uint32_t* a, uint32_t b0, uint32_t b1)
{
    asm volatile(
        "mma.sync.aligned.m16n8k32.row.col.s32.s8.s8.s32 "
        "{%0,%1,%2,%3}, {%4,%5,%6,%7}, {%8,%9}, {%0,%1,%2,%3};"
        : "+r"(d[0]), "+r"(d[1]), "+r"(d[2]), "+r"(d[3])
        : "r"(a[0]), "r"(a[1]), "r"(a[2]), "r"(a[3]), "r"(b0), "r"(b1));
}

__device__ __forceinline__ uint32_t smem_u32(const void* p)
{
    uint32_t a;
    asm("{ .reg .u64 t; cvta.to.shared.u64 t, %1; cvt.u32.u64 %0, t; }" : "=r"(a) : "l"(p));
    return a;
}

__device__ __forceinline__ void cp_async8(uint32_t dst, const void* src, int nbytes)
{
    asm volatile("cp.async.ca.shared.global [%0], [%1], 8, %2;"
                 :: "r"(dst), "l"(src), "r"(nbytes) : "memory");
}
#define CP_COMMIT() asm volatile("cp.async.commit_group;" ::: "memory")
#define CP_WAIT0()  asm volatile("cp.async.wait_group 0;" ::: "memory")

// 4-limb balanced base-2^8 decomposition (exact, verified R11)
__device__ __forceinline__ void enc8(float v, float invS, signed char* L)
{
    float u = v * invS;
    float mhf = rintf(u * 65536.f);
    float r = fmaf(mhf, -1.52587890625e-05f, u);
    int ml = (int)rintf(r * 4294967296.f);
    int mh = (int)mhf;
    int d0 = ((ml + 128) & 255) - 128;  ml = (ml - d0) >> 8;
    int d1 = ((ml + 128) & 255) - 128;  mh += (ml - d1) >> 8;
    int d2 = ((mh + 128) & 255) - 128;  mh = (mh - d2) >> 8;
    L[0] = (signed char)mh;
    L[1] = (signed char)d2;
    L[2] = (signed char)d1;
    L[3] = (signed char)d0;
}

// ---------------- prep kernels (verified) ----------------
__global__ void fold_enc_kernel(const float* __restrict__ w, const float* __restrict__ bias,
                                const float* __restrict__ g, const float* __restrict__ be,
                                const float* __restrict__ m, const float* __restrict__ v,
                                int8_t* __restrict__ wq, size_t wps,
                                float* __restrict__ bout, int CIN, int COUT)
{
    int idx = blockIdx.x * 256 + threadIdx.x;
    int total = 3 * COUT * CIN;
    if (idx < total) {
        int tap = idx / (COUT * CIN);
        int rem = idx - tap * COUT * CIN;
        int co = rem / CIN;
        int ci = rem - co * CIN;
        float scale = 1.0f;
        if (g) {
            double dinv = (double)g[co] / sqrt((double)v[co] + (double)BN_EPS);
            scale = (float)dinv;
        }
        float val = w[((size_t)co * CIN + ci) * 3 + tap] * scale;
        signed char L[4];
        enc8(val, INV_SW, L);
        #pragma unroll
        for (int p = 0; p < 4; ++p) wq[p * wps + idx] = L[p];
    }
    if (idx < COUT) {
        float bo;
        if (g) {
            double dinv = (double)g[idx] / sqrt((double)v[idx] + (double)BN_EPS);
            bo = (float)((double)bias[idx] * dinv + (double)be[idx] - (double)m[idx] * dinv);
        } else {
            bo = bias[idx];
        }
        bout[idx] = bo;
    }
}

__global__ void esq_kernel(const float* __restrict__ emb)
{
    int j = blockIdx.x * 256 + threadIdx.x;
    if (j < NCODES) {
        const float* e = emb + (size_t)j * C3;
        float s = 0.f;
        #pragma unroll 8
        for (int k = 0; k < C3; ++k) s = fmaf(e[k], e[k], s);
        g_esq[j] = s;
    }
}

__global__ __launch_bounds__(256) void xenc_kernel(const float* __restrict__ x,
                                                   int8_t* __restrict__ q, size_t qps)
{
    __shared__ float tile[32][33];
    int b = blockIdx.z, t0 = blockIdx.x * 32, c0 = blockIdx.y * 32;
    int tx = threadIdx.x & 31, ty = threadIdx.x >> 5;
    #pragma unroll
    for (int i = 0; i < 4; ++i)
        tile[ty + 8 * i][tx] = x[((size_t)b * C0 + c0 + ty + 8 * i) * L0 + t0 + tx];
    __syncthreads();
    int tl = threadIdx.x & 31;
    int c4 = threadIdx.x >> 5;
    signed char L[4][4];
    #pragma unroll
    for (int k = 0; k < 4; ++k) {
        signed char tmp[4];
        enc8(tile[c4 * 4 + k][tl], INV_SX, tmp);
        #pragma unroll
        for (int p = 0; p < 4; ++p) L[p][k] = tmp[p];
    }
    size_t o = ((size_t)b * L0 + t0 + tl) * C0 + c0 + c4 * 4;
    #pragma unroll
    for (int p = 0; p < 4; ++p)
        *(char4*)(q + p * qps + o) = make_char4(L[p][0], L[p][1], L[p][2], L[p][3]);
}

// ---------------- conv via exact int8 IMMA v7: R12 layout, warp tile m32 x n32 ----------------
// 256 threads / 8 warps (4 warpm x 2 warpn), CTA 128t x 64co, warp m32 x n32.
// 100 B of fragment LDS per MMA (vs 150 in R12) -> L1 shared-pipe relief.
// Numerics byte-identical to R11/R12 (classes 0..3 persistent int32, scalar-LDS fragments).
template<int CIN, int LIN, int LOUT, int COUT, int STRIDE, bool RELU, bool SPLITOUT>
__global__ __launch_bounds__(256, 1)
void conv_imma7_kernel(const int8_t* __restrict__ Xq, size_t xps,
                       const int8_t* __restrict__ Wq, size_t wps,
                       const float* __restrict__ bias, float fscale, float invSo,
                       int8_t* __restrict__ Yq, size_t yps,
                       float* __restrict__ Yf)
{
    constexpr int NTR = STRIDE * 128 + 2;
    constexpr int RB = 40;
    constexpr int ASTR = NTR * RB;
    constexpr int ASZ  = 4 * ASTR;
    constexpr int BSTR = 64 * RB;
    constexpr int BUFSZ = ASZ + 12 * BSTR;
    constexpr int NC = CIN / 32;
    extern __shared__ int8_t smm[];
    const uint32_t smb = smem_u32(smm);

    const int tid = threadIdx.x;
    const int lane = tid & 31;
    const int wid = tid >> 5;
    const int warpm = wid & 3;
    const int warpn = (wid >> 2) & 1;
    const int g = lane >> 2;
    const int tq = lane & 3;
    const int t0  = blockIdx.x * 128;
    const int co0 = blockIdx.y * 64;
    const int bb  = blockIdx.z;
    const int GB  = STRIDE * t0 - 1;

    int ia0[2][4][4], ia1[2][4][4], ia2[2][4][4], ia3[2][4][4];
    #pragma unroll
    for (int mt = 0; mt < 2; ++mt)
        #pragma unroll
        for (int nt = 0; nt < 4; ++nt)
            #pragma unroll
            for (int q = 0; q < 4; ++q) {
                ia0[mt][nt][q] = 0; ia1[mt][nt][q] = 0;
                ia2[mt][nt][q] = 0; ia3[mt][nt][q] = 0;
            }

    auto issue_loads = [&](int cc, uint32_t dst) {
        for (int i = tid; i < NTR * 4; i += 256) {
            int r = i >> 2, u = i & 3;
            int grow = GB + r;
            bool ok = (grow >= 0 && grow < LIN);
            size_t boff = ok ? (((size_t)bb * LIN + grow) * CIN + cc * 32) + u * 8 : 0;
            #pragma unroll
            for (int p = 0; p < 4; ++p)
                cp_async8(dst + p * ASTR + r * RB + u * 8, Xq + p * xps + boff, ok ? 8 : 0);
        }
        for (int i = tid; i < 3 * 64 * 4; i += 256) {
            int tap = i >> 8, rem = i & 255;
            int r = rem >> 2, u = rem & 3;
            size_t boff = (((size_t)tap * COUT + co0 + r) * CIN + cc * 32) + u * 8;
            #pragma unroll
            for (int p = 0; p < 4; ++p)
                cp_async8(dst + ASZ + (tap * 4 + p) * BSTR + r * RB + u * 8,
                          Wq + p * wps + boff, 8);
        }
    };

    issue_loads(0, smb);
    CP_COMMIT();
    CP_WAIT0();
    __syncthreads();

    for (int cc = 0; cc < NC; ++cc) {
        if (cc + 1 < NC) {
            issue_loads(cc + 1, smb + ((cc + 1) & 1) * BUFSZ);
            CP_COMMIT();
        }
        const int8_t* sbase = smm + (cc & 1) * BUFSZ;

        #pragma unroll
        for (int tap = 0; tap < 3; ++tap) {
            uint32_t af[4][2][4];
            #pragma unroll
            for (int mt = 0; mt < 2; ++mt) {
                int tl = warpm * 32 + mt * 16 + g;
                int ra = STRIDE * tl + tap;
                int ra8 = ra + 8 * STRIDE;
                #pragma unroll
                for (int p = 0; p < 4; ++p) {
                    const int8_t* base = sbase + p * ASTR;
                    af[p][mt][0] = *(const uint32_t*)&base[ra  * RB + tq * 4];
                    af[p][mt][1] = *(const uint32_t*)&base[ra8 * RB + tq * 4];
                    af[p][mt][2] = *(const uint32_t*)&base[ra  * RB + tq * 4 + 16];
                    af[p][mt][3] = *(const uint32_t*)&base[ra8 * RB + tq * 4 + 16];
                }
            }
            #pragma unroll
            for (int nt = 0; nt < 4; ++nt) {
                int rb = warpn * 32 + nt * 8 + g;
                uint32_t bf[4][2];
                #pragma unroll
                for (int p = 0; p < 4; ++p) {
                    const int8_t* base = sbase + ASZ + (tap * 4 + p) * BSTR;
                    bf[p][0] = *(const uint32_t*)&base[rb * RB + tq * 4];
                    bf[p][1] = *(const uint32_t*)&base[rb * RB + tq * 4 + 16];
                }
                // class 0
                mma_s8(ia0[0][nt], af[0][0], bf[0][0], bf[0][1]);
                mma_s8(ia0[1][nt], af[0][1], bf[0][0], bf[0][1]);
                // class 1
                mma_s8(ia1[0][nt], af[0][0], bf[1][0], bf[1][1]);
                mma_s8(ia1[0][nt], af[1][0], bf[0][0], bf[0][1]);
                mma_s8(ia1[1][nt], af[0][1], bf[1][0], bf[1][1]);
                mma_s8(ia1[1][nt], af[1][1], bf[0][0], bf[0][1]);
                // class 2
                mma_s8(ia2[0][nt], af[0][0], bf[2][0], bf[2][1]);
                mma_s8(ia2[0][nt], af[1][0], bf[1][0], bf[1][1]);
                mma_s8(ia2[0][nt], af[2][0], bf[0][0], bf[0][1]);
                mma_s8(ia2[1][nt], af[0][1], bf[2][0], bf[2][1]);
                mma_s8(ia2[1][nt], af[1][1], bf[1][0], bf[1][1]);
                mma_s8(ia2[1][nt], af[2][1], bf[0][0], bf[0][1]);
                // class 3
                mma_s8(ia3[0][nt], af[0][0], bf[3][0], bf[3][1]);
                mma_s8(ia3[0][nt], af[1][0], bf[2][0], bf[2][1]);
                mma_s8(ia3[0][nt], af[2][0], bf[1][0], bf[1][1]);
                mma_s8(ia3[0][nt], af[3][0], bf[0][0], bf[0][1]);
                mma_s8(ia3[1][nt], af[0][1], bf[3][0], bf[3][1]);
                mma_s8(ia3[1][nt], af[1][1], bf[2][0], bf[2][1]);
                mma_s8(ia3[1][nt], af[2][1], bf[1][0], bf[1][1]);
                mma_s8(ia3[1][nt], af[3][1], bf[0][0], bf[0][1]);
            }
        }
        CP_WAIT0();
        __syncthreads();
    }

    // ---- epilogue (identical math to R11/R12) ----
    #pragma unroll
    for (int nt = 0; nt < 4; ++nt) {
        int cog = co0 + warpn * 32 + nt * 8 + tq * 2;
        float b0 = __ldg(&bias[cog]);
        float b1 = __ldg(&bias[cog + 1]);
        #pragma unroll
        for (int mt = 0; mt < 2; ++mt) {
            #pragma unroll
            for (int half = 0; half < 2; ++half) {
                int t = t0 + warpm * 32 + mt * 16 + g + half * 8;
                int q0 = half * 2, q1 = half * 2 + 1;
                float s0 = __int2float_rn(ia0[mt][nt][q0])
                         + __int2float_rn(ia1[mt][nt][q0]) * 0.00390625f
                         + __int2float_rn(ia2[mt][nt][q0]) * 1.52587890625e-05f
                         + __int2float_rn(ia3[mt][nt][q0]) * 5.9604644775390625e-08f;
                float s1 = __int2float_rn(ia0[mt][nt][q1])
                         + __int2float_rn(ia1[mt][nt][q1]) * 0.00390625f
                         + __int2float_rn(ia2[mt][nt][q1]) * 1.52587890625e-05f
                         + __int2float_rn(ia3[mt][nt][q1]) * 5.9604644775390625e-08f;
                float v0 = fmaf(s0, fscale, b0);
                float v1 = fmaf(s1, fscale, b1);
                if (RELU) {
                    v0 = (v0 >= 0.f) ? v0 : 0.01f * v0;
                    v1 = (v1 >= 0.f) ? v1 : 0.01f * v1;
                }
                if (SPLITOUT) {
                    signed char La[4], Lb[4];
                    enc8(v0, invSo, La);
                    enc8(v1, invSo, Lb);
                    size_t o = ((size_t)bb * LOUT + t) * COUT + cog;
                    #pragma unroll
                    for (int p = 0; p < 4; ++p) {
                        unsigned short pk = (unsigned short)((unsigned char)La[p]
                                          | ((unsigned short)(unsigned char)Lb[p] << 8));
                        *(unsigned short*)(Yq + p * yps + o) = pk;
                    }
                } else {
                    *(float2*)(Yf + ((size_t)bb * LOUT + t) * COUT + cog) = make_float2(v0, v1);
                }
            }
        }
    }
}

// ---------------- VQ splits (verified R3) ----------------
__global__ __launch_bounds__(256) void split_z_kernel(const float* __restrict__ zz)
{
    int idx = blockIdx.x * 256 + threadIdx.x;
    int row = idx >> 4, gs = idx & 15;
    const float* zr = zz + (size_t)row * C3 + gs * 8;
    float4 p0 = *(const float4*)zr;
    float4 p1 = *(const float4*)(zr + 4);
    float v[8] = {p0.x, p0.y, p0.z, p0.w, p1.x, p1.y, p1.z, p1.w};
    unsigned short h[8], l[8];
    #pragma unroll
    for (int e = 0; e < 8; ++e) bsplit2(v[e], h[e], l[e]);
    ((uint4*)g_zhi)[(size_t)row * 16 + gs] = pack8u(h);
    ((uint4*)g_zlo)[(size_t)row * 16 + gs] = pack8u(l);
    if (gs == 0) {
        const float* zf = zz + (size_t)row * C3;
        float a = 0.f;
        #pragma unroll 8
        for (int k = 0; k < C3; ++k) a = fmaf(zf[k], zf[k], a);
        g_arow[row] = a;
    }
}

__global__ __launch_bounds__(256) void split_e_kernel(const float* __restrict__ emb)
{
    int idx = blockIdx.x * 256 + threadIdx.x;
    int row = idx >> 4, gs = idx & 15;
    const float* er = emb + (size_t)row * C3 + gs * 8;
    float4 p0 = *(const float4*)er;
    float4 p1 = *(const float4*)(er + 4);
    float v[8] = {p0.x, p0.y, p0.z, p0.w, p1.x, p1.y, p1.z, p1.w};
    unsigned short h[8], l[8];
    #pragma unroll
    for (int e = 0; e < 8; ++e) bsplit2(v[e], h[e], l[e]);
    ((uint4*)g_ehi)[(size_t)row * 16 + gs] = pack8u(h);
    ((uint4*)g_elo)[(size_t)row * 16 + gs] = pack8u(l);
}

// ---------------- VQ on mma.sync (verified R3, unchanged) ----------------
#define ZH_OFF 0
#define ZL_OFF 34816
#define EH_OFF 69632
#define EL_OFF 87040
#define JF_OFF 104448
#define RV_OFF 104960
#define RJ_OFF 105984
#define VQ_DYN 107520
#define ROWPAD 272

__global__ __launch_bounds__(256, 1)
void vq_mma_kernel(const float* __restrict__ esq, const float* __restrict__ arow,
                   const float* __restrict__ emb,
                   float* __restrict__ codes, float* __restrict__ quant)
{
    extern __shared__ char smc[];
    const int tid = threadIdx.x;
    const int lane = tid & 31;
    const int wid = tid >> 5;
    const int warp_m = wid & 3;
    const int warp_n = wid >> 2;
    const int g = lane >> 2;
    const int tq = lane & 3;
    const int n0 = blockIdx.x * 128;
    const int mbase = warp_m * 32;

    for (int i = tid; i < 128 * 32; i += 256) {
        int row = i >> 5, u = i & 31;
        ((uint2*)(smc + ZH_OFF))[row * 34 + u] = ((const uint2*)g_zhi)[(size_t)(n0 + row) * 32 + u];
        ((uint2*)(smc + ZL_OFF))[row * 34 + u] = ((const uint2*)g_zlo)[(size_t)(n0 + row) * 32 + u];
    }

    float aval[4];
    #pragma unroll
    for (int s = 0; s < 4; ++s)
        aval[s] = __ldg(&arow[n0 + mbase + (s >> 1) * 16 + (s & 1) * 8 + g]);

    float best[4] = {3.4e38f, 3.4e38f, 3.4e38f, 3.4e38f};
    int   bj[4]   = {0, 0, 0, 0};

    for (int c = 0; c < 64; ++c) {
        __syncthreads();
        for (int i = tid; i < 64 * 32; i += 256) {
            int row = i >> 5, u = i & 31;
            ((uint2*)(smc + EH_OFF))[row * 34 + u] = ((const uint2*)g_ehi)[(size_t)(c * 64 + row) * 32 + u];
            ((uint2*)(smc + EL_OFF))[row * 34 + u] = ((const uint2*)g_elo)[(size_t)(c * 64 + row) * 32 + u];
        }
        __syncthreads();

        float acc[2][4][4];
        #pragma unroll
        for (int mt = 0; mt < 2; ++mt)
            #pragma unroll
            for (int nt = 0; nt < 4; ++nt)
                #pragma unroll
                for (int q = 0; q < 4; ++q) acc[mt][nt][q] = 0.f;

        #pragma unroll
        for (int ks = 0; ks < 8; ++ks) {
            const int k0 = ks * 16;
            uint32_t ah[2][4], al[2][4];
            #pragma unroll
            for (int mt = 0; mt < 2; ++mt) {
                int r0 = mbase + mt * 16 + g;
                int cb = (k0 + tq * 2) * 2;
                ah[mt][0] = *(const uint32_t*)(smc + ZH_OFF + r0 * ROWPAD + cb);
                ah[mt][1] = *(const uint32_t*)(smc + ZH_OFF + (r0 + 8) * ROWPAD + cb);
                ah[mt][2] = *(const uint32_t*)(smc + ZH_OFF + r0 * ROWPAD + cb + 16);
                ah[mt][3] = *(const uint32_t*)(smc + ZH_OFF + (r0 + 8) * ROWPAD + cb + 16);
                al[mt][0] = *(const uint32_t*)(smc + ZL_OFF + r0 * ROWPAD + cb);
                al[mt][1] = *(const uint32_t*)(smc + ZL_OFF + (r0 + 8) * ROWPAD + cb);
                al[mt][2] = *(const uint32_t*)(smc + ZL_OFF + r0 * ROWPAD + cb + 16);
                al[mt][3] = *(const uint32_t*)(smc + ZL_OFF + (r0 + 8) * ROWPAD + cb + 16);
            }
            #pragma unroll
            for (int nt = 0; nt < 4; ++nt) {
                int nrow = warp_n * 32 + nt * 8 + g;
                int cb = (k0 + tq * 2) * 2;
                uint32_t bh0 = *(const uint32_t*)(smc + EH_OFF + nrow * ROWPAD + cb);
                uint32_t bh1 = *(const uint32_t*)(smc + EH_OFF + nrow * ROWPAD + cb + 16);
                uint32_t bl0 = *(const uint32_t*)(smc + EL_OFF + nrow * ROWPAD + cb);
                uint32_t bl1 = *(const uint32_t*)(smc + EL_OFF + nrow * ROWPAD + cb + 16);
                #pragma unroll
                for (int mt = 0; mt < 2; ++mt) {
                    mma_bf16(acc[mt][nt], ah[mt], bh0, bh1);
                    mma_bf16(acc[mt][nt], ah[mt], bl0, bl1);
                    mma_bf16(acc[mt][nt], al[mt], bh0, bh1);
                }
            }
        }

        #pragma unroll
        for (int nt = 0; nt < 4; ++nt) {
            int jb = c * 64 + warp_n * 32 + nt * 8 + tq * 2;
            float e0 = __ldg(&esq[jb]);
            float e1 = __ldg(&esq[jb + 1]);
            #pragma unroll
            for (int mt = 0; mt < 2; ++mt) {
                int s0 = mt * 2, s1 = mt * 2 + 1;
                float d;
                d = (aval[s0] + e0) - 2.0f * acc[mt][nt][0];
                if (d < best[s0]) { best[s0] = d; bj[s0] = jb; }
                d = (aval[s0] + e1) - 2.0f * acc[mt][nt][1];
                if (d < best[s0]) { best[s0] = d; bj[s0] = jb + 1; }
                d = (aval[s1] + e0) - 2.0f * acc[mt][nt][2];
                if (d < best[s1]) { best[s1] = d; bj[s1] = jb; }
                d = (aval[s1] + e1) - 2.0f * acc[mt][nt][3];
                if (d < best[s1]) { best[s1] = d; bj[s1] = jb + 1; }
            }
        }
    }

    #pragma unroll
    for (int s = 0; s < 4; ++s) {
        #pragma unroll
        for (int off = 2; off >= 1; off >>= 1) {
            float ov = __shfl_xor_sync(0xffffffffu, best[s], off);
            int   oj = __shfl_xor_sync(0xffffffffu, bj[s],   off);
            if (ov < best[s] || (ov == best[s] && oj < bj[s])) { best[s] = ov; bj[s] = oj; }
        }
    }
    float* rv = (float*)(smc + RV_OFF);
    int*   rj = (int*)(smc + RJ_OFF);
    if (tq == 0) {
        #pragma unroll
        for (int s = 0; s < 4; ++s) {
            int row = mbase + (s >> 1) * 16 + (s & 1) * 8 + g;
            rv[row * 2 + warp_n] = best[s];
            rj[row * 2 + warp_n] = bj[s];
        }
    }
    __syncthreads();

    int* jf = (int*)(smc + JF_OFF);
    if (tid < 128) {
        float v0 = rv[tid * 2], v1 = rv[tid * 2 + 1];
        int   j0 = rj[tid * 2], j1 = rj[tid * 2 + 1];
        int j = (v1 < v0 || (v1 == v0 && j1 < j0)) ? j1 : j0;
        jf[tid] = j;
        codes[n0 + tid] = (float)j;
    }
    __syncthreads();

    for (int i = tid; i < 128 * 32; i += 256) {
        int row = i >> 5, q = i & 31;
        int j = jf[row];
        float4 v = __ldg((const float4*)emb + (size_t)j * 32 + q);
        ((float4*)quant)[(size_t)(n0 + row) * 32 + q] = v;
    }
}

// ---------------- host launch ----------------
static void* sym(const void* s) { void* p = nullptr; cudaGetSymbolAddress(&p, s); return p; }

#define C12_SMEM (2 * (4 * 258 * 40 + 12 * 64 * 40))   // 144000
#define C3_SMEM  (2 * (4 * 130 * 40 + 12 * 64 * 40))   // 103040

extern "C" void kernel_launch(void* const* d_in, const int* in_sizes, int n_in,
                              void* d_out, int out_size)
{
    const float* x       = (const float*)d_in[0];
    const float* conv1_w = (const float*)d_in[1];
    const float* conv1_b = (const float*)d_in[2];
    const float* bn1_g   = (const float*)d_in[3];
    const float* bn1_b   = (const float*)d_in[4];
    const float* bn1_m   = (const float*)d_in[5];
    const float* bn1_v   = (const float*)d_in[6];
    const float* conv2_w = (const float*)d_in[7];
    const float* conv2_b = (const float*)d_in[8];
    const float* bn2_g   = (const float*)d_in[9];
    const float* bn2_b   = (const float*)d_in[10];
    const float* bn2_m   = (const float*)d_in[11];
    const float* bn2_v   = (const float*)d_in[12];
    const float* conv3_w = (const float*)d_in[13];
    const float* conv3_b = (const float*)d_in[14];
    const float* emb     = (const float*)d_in[15];

    float* bb1 = (float*)sym(g_bb1);
    float* bb2 = (float*)sym(g_bb2);
    float* bb3 = (float*)sym(g_bb3);
    float* zz  = (float*)sym(g_zz);
    float* esq = (float*)sym(g_esq);
    float* arw = (float*)sym(g_arow);
    int8_t* xq  = (int8_t*)sym(g_xq);
    int8_t* h1q = (int8_t*)sym(g_h1q);
    int8_t* h2q = (int8_t*)sym(g_h2q);
    int8_t* w1q = (int8_t*)sym(g_w1q);
    int8_t* w2q = (int8_t*)sym(g_w2q);
    int8_t* w3q = (int8_t*)sym(g_w3q);

    float* out = (float*)d_out;
    float* codes_ptr;
    float* quant_ptr;
    const int FULL = NROWS + NROWS * C3;
    if (out_size >= FULL)            { codes_ptr = out; quant_ptr = out + NROWS; }
    else if (out_size == NROWS * C3) { codes_ptr = (float*)sym(g_dummy_codes); quant_ptr = out; }
    else if (out_size == NROWS)      { codes_ptr = out; quant_ptr = (float*)sym(g_dummy_q); }
    else                             { codes_ptr = out; quant_ptr = out + NROWS; }

    cudaFuncSetAttribute(vq_mma_kernel, cudaFuncAttributeMaxDynamicSharedMemorySize, VQ_DYN);
    cudaFuncSetAttribute((const void*)conv_imma7_kernel<C0, L0, L1, C1, 2, true, true>,
                         cudaFuncAttributeMaxDynamicSharedMemorySize, C12_SMEM);
    cudaFuncSetAttribute((const void*)conv_imma7_kernel<C1, L1, L2, C2, 2, true, true>,
                         cudaFuncAttributeMaxDynamicSharedMemorySize, C12_SMEM);
    cudaFuncSetAttribute((const void*)conv_imma7_kernel<C2, L2, L2, C3, 1, false, false>,
                         cudaFuncAttributeMaxDynamicSharedMemorySize, C3_SMEM);

    // Launch order keeps conv1 at the ncu-captured index.
    {
        dim3 gx(L0 / 32, C0 / 32, BATCH);
        xenc_kernel<<<gx, 256>>>(x, xq, XQN);
    }
    fold_enc_kernel<<<(3 * C1 * C0 + 255) / 256, 256>>>(conv1_w, conv1_b, bn1_g, bn1_b, bn1_m, bn1_v,
                                                        w1q, W1N, bb1, C0, C1);
    fold_enc_kernel<<<(3 * C2 * C1 + 255) / 256, 256>>>(conv2_w, conv2_b, bn2_g, bn2_b, bn2_m, bn2_v,
                                                        w2q, W2N, bb2, C1, C2);
    {
        dim3 g1(L1 / 128, C1 / 64, BATCH);
        conv_imma7_kernel<C0, L0, L1, C1, 2, true, true><<<g1, 256, C12_SMEM>>>(
            xq, XQN, w1q, W1N, bb1, FSCALE1, INV_SH, h1q, H1N, nullptr);
    }
    fold_enc_kernel<<<(3 * C3 * C2 + 255) / 256, 256>>>(conv3_w, conv3_b, nullptr, nullptr, nullptr, nullptr,
                                                        w3q, W3N, bb3, C2, C3);
    esq_kernel<<<(NCODES + 255) / 256, 256>>>(emb);
    split_e_kernel<<<(NCODES * 16) / 256, 256>>>(emb);
    {
        dim3 g2(L2 / 128, C2 / 64, BATCH);
        conv_imma7_kernel<C1, L1, L2, C2, 2, true, true><<<g2, 256, C12_SMEM>>>(
            h1q, H1N, w2q, W2N, bb2, FSCALE2, INV_SH, h2q, H2N, nullptr);
    }
    {
        dim3 g3(L2 / 128, C3 / 64, BATCH);
        conv_imma7_kernel<C2, L2, L2, C3, 1, false, false><<<g3, 256, C3_SMEM>>>(
            h2q, H2N, w3q, W3N, bb3, FSCALE3, 0.f, nullptr, 0, zz);
    }
    split_z_kernel<<<(NROWS * 16) / 256, 256>>>(zz);
    vq_mma_kernel<<<NROWS / 128, 256, VQ_DYN>>>(esq, arw, emb, codes_ptr, quant_ptr);
}